// round 8
// baseline (speedup 1.0000x reference)
#include <cuda_runtime.h>
#include <cstdint>

#define B_ 512
#define T_ 2048
#define S_ 128
#define P_ 1985
#define THREADS 512
#define BPSTRIDE 33   // u32 stride for packed shapelet rows (conflict spread)

// smem floats: xr[2176] | xp[2176] | Bp[128*33] | p2cn[2048] | s2[128] | wmax[256]
#define SMEM_FLOATS (2176 + 2176 + 128 * BPSTRIDE + 2048 + 128 + 256)
#define SMEM_BYTES  (SMEM_FLOATS * 4)

extern __shared__ float smf[];

static __device__ __forceinline__ uint32_t pack_bf16x2(float lo, float hi) {
    uint32_t r;  // d.hi = cvt(%1), d.lo = cvt(%2)
    asm("cvt.rn.bf16x2.f32 %0, %1, %2;" : "=r"(r) : "f"(hi), "f"(lo));
    return r;
}

// bf16 m16n8k16: D = A*B + {c01,c01,c23,c23}  (C as separate input operands)
static __device__ __forceinline__ void mma16_init(float d[4],
        uint32_t a0, uint32_t a1, uint32_t a2, uint32_t a3,
        uint32_t b0, uint32_t b1, float c01, float c23) {
    asm volatile(
        "mma.sync.aligned.m16n8k16.row.col.f32.bf16.bf16.f32 "
        "{%0,%1,%2,%3}, {%4,%5,%6,%7}, {%8,%9}, {%10,%10,%11,%11};"
        : "=f"(d[0]), "=f"(d[1]), "=f"(d[2]), "=f"(d[3])
        : "r"(a0), "r"(a1), "r"(a2), "r"(a3), "r"(b0), "r"(b1),
          "f"(c01), "f"(c23));
}
// bf16 m16n8k16: D = A*B + D
static __device__ __forceinline__ void mma16_acc(float d[4],
        uint32_t a0, uint32_t a1, uint32_t a2, uint32_t a3,
        uint32_t b0, uint32_t b1) {
    asm volatile(
        "mma.sync.aligned.m16n8k16.row.col.f32.bf16.bf16.f32 "
        "{%0,%1,%2,%3}, {%4,%5,%6,%7}, {%8,%9}, {%0,%1,%2,%3};"
        : "+f"(d[0]), "+f"(d[1]), "+f"(d[2]), "+f"(d[3])
        : "r"(a0), "r"(a1), "r"(a2), "r"(a3), "r"(b0), "r"(b1));
}

// One CTA per batch sample; 16 warps = 2 m-halves x 8 column groups.
// Shapelets packed as 2*(s-mean) in bf16; acc = 2*dot - pc (C-operand init);
// min d2 = s2 - max(acc). Stats (p2cn, s2) exact fp32 from raw x.
__global__ void __launch_bounds__(THREADS, 2)
shapelet_mma_kernel(const float* __restrict__ x,
                    const float* __restrict__ sh,
                    float* __restrict__ out) {
    float*    xr   = smf;                        // raw x row, zero-padded to 2176
    uint32_t* xp   = reinterpret_cast<uint32_t*>(smf + 2176);  // bf16 pairs (x[i],x[i+1])
    uint32_t* Bp   = reinterpret_cast<uint32_t*>(smf + 4352);  // 2*(s-mean) bf16 pairs
    float*    p2cn = smf + 4352 + 128 * BPSTRIDE;  // NEGATED centered window sq-norm
    float*    s2   = p2cn + 2048;                  // RAW shapelet sq-norm
    float*    wmax = s2 + 128;                     // per-half per-col maxes, 2*128

    const int tid = threadIdx.x, b = blockIdx.x;
    const int wid = tid >> 5, lane = tid & 31;
    const int gid = lane >> 2, tig = lane & 3;

    // ---- raw x row ----
    const float* xg = x + (size_t)b * T_;
    for (int i = tid; i < 2176; i += THREADS)
        xr[i] = (i < T_) ? xg[i] : 0.f;
    __syncthreads();

    // ---- pack bf16 pairs of x ----
    for (int i = tid; i < 2176; i += THREADS) {
        float hi = (i + 1 < 2176) ? xr[i + 1] : 0.f;
        xp[i] = pack_bf16x2(xr[i], hi);
    }

    // ---- shapelets: pack 2*(s-mean); s2 = RAW squared norm ----
    if (tid < S_) {
        const float* sp = sh + tid * 64;
        float sm = 0.f, q2raw = 0.f;
#pragma unroll
        for (int l = 0; l < 64; ++l) {
            float v = sp[l];
            sm += v;
            q2raw = fmaf(v, v, q2raw);
        }
        float mean = sm * (1.f / 64.f);
#pragma unroll
        for (int l = 0; l < 32; ++l)
            Bp[tid * BPSTRIDE + l] =
                pack_bf16x2(2.f * (sp[2 * l] - mean), 2.f * (sp[2 * l + 1] - mean));
        s2[tid] = q2raw;
    }

    // ---- window stats (negated) in exact fp32: 4 windows/thread ----
    {
        int p0 = tid * 4;
        float s = 0.f, qq = 0.f;
#pragma unroll
        for (int l = 0; l < 64; ++l) {
            float v = xr[p0 + l];
            s += v;
            qq = fmaf(v, v, qq);
        }
        p2cn[p0] = (p0 < P_) ? -fmaf(-s, s * (1.f / 64.f), qq) : -3.0e30f;
#pragma unroll
        for (int k = 1; k < 4; ++k) {
            float vo = xr[p0 + k - 1], vi = xr[p0 + 63 + k];
            s += vi - vo;
            qq += fmaf(vi, vi, -vo * vo);
            int p = p0 + k;
            p2cn[p] = (p < P_) ? -fmaf(-s, s * (1.f / 64.f), qq) : -3.0e30f;
        }
    }
    __syncthreads();

    // ---- persistent B fragments: 2 n-chunks x 4 k16-chunks x 2 regs ----
    const int h = wid >> 3, q = wid & 7;
    uint32_t Bf[2][4][2];
#pragma unroll
    for (int nc = 0; nc < 2; ++nc) {
        int row = q * 16 + nc * 8 + gid;
#pragma unroll
        for (int kc = 0; kc < 4; ++kc) {
            Bf[nc][kc][0] = Bp[row * BPSTRIDE + tig + 8 * kc];
            Bf[nc][kc][1] = Bp[row * BPSTRIDE + tig + 4 + 8 * kc];
        }
    }

    float mn[4] = {-3.4e38f, -3.4e38f, -3.4e38f, -3.4e38f};
    const int mstart = h * 1024;

    // ---- main loop: 64 m-groups; 16-slot A-word register ring, shift 2/mg.
    // v slot (2*mg + j) mod 16 holds xp[e0 + 8*(2*mg + j)] — only 2 new LDS
    // per m-group; inner unroll of 8 makes all slot indices static. ----
    uint32_t v[16];
    const int e0 = mstart + gid + 2 * tig;
#pragma unroll
    for (int i = 0; i < 9; ++i) v[i] = xp[e0 + 8 * i];
    int rb = mstart + gid;      // p2cn row base (window of fragment row gid)
    int av = e0;                // A-word base
    float ph0 = p2cn[rb], ph1 = p2cn[rb + 8];

    for (int o = 0; o < 8; ++o) {
#pragma unroll
        for (int u = 0; u < 8; ++u) {
            // prefetch next mg's stats + 2 new ring words (used 1 mg ahead;
            // tail prefetches overrun into padded xp / s2 smem — unused)
            float nh0 = p2cn[rb + 16], nh1 = p2cn[rb + 24];
            v[(2 * u + 9) & 15]  = xp[av + 72];
            v[(2 * u + 10) & 15] = xp[av + 80];

            float A0[4], A1[4];
            {
                uint32_t a0 = v[(2 * u) & 15], a1 = v[(2 * u + 1) & 15],
                         a3 = v[(2 * u + 2) & 15];
                mma16_init(A0, a0, a1, a1, a3, Bf[0][0][0], Bf[0][0][1], ph0, ph1);
                mma16_init(A1, a0, a1, a1, a3, Bf[1][0][0], Bf[1][0][1], ph0, ph1);
            }
#pragma unroll
            for (int kc = 1; kc < 4; ++kc) {
                uint32_t a0 = v[(2 * u + 2 * kc) & 15],
                         a1 = v[(2 * u + 2 * kc + 1) & 15],
                         a3 = v[(2 * u + 2 * kc + 2) & 15];
                mma16_acc(A0, a0, a1, a1, a3, Bf[0][kc][0], Bf[0][kc][1]);
                mma16_acc(A1, a0, a1, a1, a3, Bf[1][kc][0], Bf[1][kc][1]);
            }
            mn[0] = fmaxf(mn[0], fmaxf(A0[0], A0[2]));
            mn[1] = fmaxf(mn[1], fmaxf(A0[1], A0[3]));
            mn[2] = fmaxf(mn[2], fmaxf(A1[0], A1[2]));
            mn[3] = fmaxf(mn[3], fmaxf(A1[1], A1[3]));
            ph0 = nh0; ph1 = nh1;
            rb += 16; av += 16;
        }
    }

    // ---- reduce (max) over the 8 row-groups ----
#pragma unroll
    for (int i = 0; i < 4; ++i) {
        int nc = i >> 1, e = i & 1;
        float m = mn[i];
        m = fmaxf(m, __shfl_xor_sync(0xffffffffu, m, 4));
        m = fmaxf(m, __shfl_xor_sync(0xffffffffu, m, 8));
        m = fmaxf(m, __shfl_xor_sync(0xffffffffu, m, 16));
        if (lane < 4)
            wmax[h * 128 + q * 16 + nc * 8 + lane * 2 + e] = m;
    }
    __syncthreads();

    // ---- combine m-halves: min d2 = s2 - max(acc); sqrt; store ----
    if (tid < S_) {
        float mv = fmaxf(wmax[tid], wmax[128 + tid]);
        float d2 = s2[tid] - mv;
        out[(size_t)b * S_ + tid] = sqrtf(fmaxf(d2, 0.f));
    }
}

extern "C" void kernel_launch(void* const* d_in, const int* in_sizes, int n_in,
                              void* d_out, int out_size) {
    const float* x  = (const float*)d_in[0];   // (512, 1, 2048) fp32
    const float* sh = (const float*)d_in[1];   // (128, 1, 64)   fp32
    float* out = (float*)d_out;                // (512, 128)     fp32
    cudaFuncSetAttribute(shapelet_mma_kernel,
                         cudaFuncAttributeMaxDynamicSharedMemorySize, SMEM_BYTES);
    shapelet_mma_kernel<<<B_, THREADS, SMEM_BYTES>>>(x, sh, out);
}

// round 9
// speedup vs baseline: 1.0009x; 1.0009x over previous
#include <cuda_runtime.h>
#include <cstdint>

#define B_ 512
#define T_ 2048
#define S_ 128
#define P_ 1985
#define THREADS 512
#define BPSTRIDE 33   // u32 stride for packed shapelet rows (conflict spread)

// smem floats: xr[2176] | xp[2176] | Bp[128*33] | p2cn[2048] | s2[128] | wmax[256]
#define SMEM_FLOATS (2176 + 2176 + 128 * BPSTRIDE + 2048 + 128 + 256)
#define SMEM_BYTES  (SMEM_FLOATS * 4)

extern __shared__ float smf[];

static __device__ __forceinline__ uint32_t pack_bf16x2(float lo, float hi) {
    uint32_t r;  // d.hi = cvt(%1), d.lo = cvt(%2)
    asm("cvt.rn.bf16x2.f32 %0, %1, %2;" : "=r"(r) : "f"(hi), "f"(lo));
    return r;
}

// bf16 m16n8k16: D = A*B + {c01,c01,c23,c23}  (C as separate input operands)
static __device__ __forceinline__ void mma16_init(float d[4],
        uint32_t a0, uint32_t a1, uint32_t a2, uint32_t a3,
        uint32_t b0, uint32_t b1, float c01, float c23) {
    asm volatile(
        "mma.sync.aligned.m16n8k16.row.col.f32.bf16.bf16.f32 "
        "{%0,%1,%2,%3}, {%4,%5,%6,%7}, {%8,%9}, {%10,%10,%11,%11};"
        : "=f"(d[0]), "=f"(d[1]), "=f"(d[2]), "=f"(d[3])
        : "r"(a0), "r"(a1), "r"(a2), "r"(a3), "r"(b0), "r"(b1),
          "f"(c01), "f"(c23));
}
// bf16 m16n8k16: D = A*B + D
static __device__ __forceinline__ void mma16_acc(float d[4],
        uint32_t a0, uint32_t a1, uint32_t a2, uint32_t a3,
        uint32_t b0, uint32_t b1) {
    asm volatile(
        "mma.sync.aligned.m16n8k16.row.col.f32.bf16.bf16.f32 "
        "{%0,%1,%2,%3}, {%4,%5,%6,%7}, {%8,%9}, {%0,%1,%2,%3};"
        : "+f"(d[0]), "+f"(d[1]), "+f"(d[2]), "+f"(d[3])
        : "r"(a0), "r"(a1), "r"(a2), "r"(a3), "r"(b0), "r"(b1));
}

// One CTA per batch sample; 16 warps = 2 m-halves x 8 column groups.
// Shapelets packed as 2*(s-mean) in bf16; acc = 2*dot - pc (C-operand init);
// min d2 = s2 - max(acc). Stats (p2cn, s2) exact fp32 from raw x.
__global__ void __launch_bounds__(THREADS, 2)
shapelet_mma_kernel(const float* __restrict__ x,
                    const float* __restrict__ sh,
                    float* __restrict__ out) {
    float*    xr   = smf;                        // raw x row, zero-padded to 2176
    uint32_t* xp   = reinterpret_cast<uint32_t*>(smf + 2176);  // bf16 pairs (x[i],x[i+1])
    uint32_t* Bp   = reinterpret_cast<uint32_t*>(smf + 4352);  // 2*(s-mean) bf16 pairs
    float*    p2cn = smf + 4352 + 128 * BPSTRIDE;  // NEGATED centered window sq-norm
    float*    s2   = p2cn + 2048;                  // RAW shapelet sq-norm
    float*    wmax = s2 + 128;                     // per-half per-col maxes, 2*128

    const int tid = threadIdx.x, b = blockIdx.x;
    const int wid = tid >> 5, lane = tid & 31;
    const int gid = lane >> 2, tig = lane & 3;

    // ---- raw x row ----
    const float* xg = x + (size_t)b * T_;
    for (int i = tid; i < 2176; i += THREADS)
        xr[i] = (i < T_) ? xg[i] : 0.f;
    __syncthreads();

    // ---- pack bf16 pairs of x ----
    for (int i = tid; i < 2176; i += THREADS) {
        float hi = (i + 1 < 2176) ? xr[i + 1] : 0.f;
        xp[i] = pack_bf16x2(xr[i], hi);
    }

    // ---- shapelets: pack 2*(s-mean); s2 = RAW squared norm ----
    if (tid < S_) {
        const float* sp = sh + tid * 64;
        float sm = 0.f, q2raw = 0.f;
#pragma unroll
        for (int l = 0; l < 64; ++l) {
            float v = sp[l];
            sm += v;
            q2raw = fmaf(v, v, q2raw);
        }
        float mean = sm * (1.f / 64.f);
#pragma unroll
        for (int l = 0; l < 32; ++l)
            Bp[tid * BPSTRIDE + l] =
                pack_bf16x2(2.f * (sp[2 * l] - mean), 2.f * (sp[2 * l + 1] - mean));
        s2[tid] = q2raw;
    }

    // ---- window stats (negated) in exact fp32: 4 windows/thread ----
    {
        int p0 = tid * 4;
        float s = 0.f, qq = 0.f;
#pragma unroll
        for (int l = 0; l < 64; ++l) {
            float v = xr[p0 + l];
            s += v;
            qq = fmaf(v, v, qq);
        }
        p2cn[p0] = (p0 < P_) ? -fmaf(-s, s * (1.f / 64.f), qq) : -3.0e30f;
#pragma unroll
        for (int k = 1; k < 4; ++k) {
            float vo = xr[p0 + k - 1], vi = xr[p0 + 63 + k];
            s += vi - vo;
            qq += fmaf(vi, vi, -vo * vo);
            int p = p0 + k;
            p2cn[p] = (p < P_) ? -fmaf(-s, s * (1.f / 64.f), qq) : -3.0e30f;
        }
    }
    __syncthreads();

    // ---- persistent B fragments: 2 n-chunks x 4 k16-chunks x 2 regs ----
    const int h = wid >> 3, q = wid & 7;
    uint32_t Bf[2][4][2];
#pragma unroll
    for (int nc = 0; nc < 2; ++nc) {
        int row = q * 16 + nc * 8 + gid;
#pragma unroll
        for (int kc = 0; kc < 4; ++kc) {
            Bf[nc][kc][0] = Bp[row * BPSTRIDE + tig + 8 * kc];
            Bf[nc][kc][1] = Bp[row * BPSTRIDE + tig + 4 + 8 * kc];
        }
    }

    float mn[4] = {-3.4e38f, -3.4e38f, -3.4e38f, -3.4e38f};
    const int mstart = h * 1024;

    // ---- main loop: 64 m-groups; 16-slot A-word register ring, shift 2/mg.
    // v slot (2*mg + j) mod 16 holds xp[e0 + 8*(2*mg + j)] — only 2 new LDS
    // per m-group; inner unroll of 8 makes all slot indices static. ----
    uint32_t v[16];
    const int e0 = mstart + gid + 2 * tig;
#pragma unroll
    for (int i = 0; i < 9; ++i) v[i] = xp[e0 + 8 * i];
    int rb = mstart + gid;      // p2cn row base (window of fragment row gid)
    int av = e0;                // A-word base
    float ph0 = p2cn[rb], ph1 = p2cn[rb + 8];

    for (int o = 0; o < 8; ++o) {
#pragma unroll
        for (int u = 0; u < 8; ++u) {
            // prefetch next mg's stats + 2 new ring words (used 1 mg ahead;
            // tail prefetches overrun into padded xp / s2 smem — unused)
            float nh0 = p2cn[rb + 16], nh1 = p2cn[rb + 24];
            v[(2 * u + 9) & 15]  = xp[av + 72];
            v[(2 * u + 10) & 15] = xp[av + 80];

            float A0[4], A1[4];
            {
                uint32_t a0 = v[(2 * u) & 15], a1 = v[(2 * u + 1) & 15],
                         a3 = v[(2 * u + 2) & 15];
                mma16_init(A0, a0, a1, a1, a3, Bf[0][0][0], Bf[0][0][1], ph0, ph1);
                mma16_init(A1, a0, a1, a1, a3, Bf[1][0][0], Bf[1][0][1], ph0, ph1);
            }
#pragma unroll
            for (int kc = 1; kc < 4; ++kc) {
                uint32_t a0 = v[(2 * u + 2 * kc) & 15],
                         a1 = v[(2 * u + 2 * kc + 1) & 15],
                         a3 = v[(2 * u + 2 * kc + 2) & 15];
                mma16_acc(A0, a0, a1, a1, a3, Bf[0][kc][0], Bf[0][kc][1]);
                mma16_acc(A1, a0, a1, a1, a3, Bf[1][kc][0], Bf[1][kc][1]);
            }
            mn[0] = fmaxf(mn[0], fmaxf(A0[0], A0[2]));
            mn[1] = fmaxf(mn[1], fmaxf(A0[1], A0[3]));
            mn[2] = fmaxf(mn[2], fmaxf(A1[0], A1[2]));
            mn[3] = fmaxf(mn[3], fmaxf(A1[1], A1[3]));
            ph0 = nh0; ph1 = nh1;
            rb += 16; av += 16;
        }
    }

    // ---- reduce (max) over the 8 row-groups ----
#pragma unroll
    for (int i = 0; i < 4; ++i) {
        int nc = i >> 1, e = i & 1;
        float m = mn[i];
        m = fmaxf(m, __shfl_xor_sync(0xffffffffu, m, 4));
        m = fmaxf(m, __shfl_xor_sync(0xffffffffu, m, 8));
        m = fmaxf(m, __shfl_xor_sync(0xffffffffu, m, 16));
        if (lane < 4)
            wmax[h * 128 + q * 16 + nc * 8 + lane * 2 + e] = m;
    }
    __syncthreads();

    // ---- combine m-halves: min d2 = s2 - max(acc); sqrt; store ----
    if (tid < S_) {
        float mv = fmaxf(wmax[tid], wmax[128 + tid]);
        float d2 = s2[tid] - mv;
        out[(size_t)b * S_ + tid] = sqrtf(fmaxf(d2, 0.f));
    }
}

extern "C" void kernel_launch(void* const* d_in, const int* in_sizes, int n_in,
                              void* d_out, int out_size) {
    const float* x  = (const float*)d_in[0];   // (512, 1, 2048) fp32
    const float* sh = (const float*)d_in[1];   // (128, 1, 64)   fp32
    float* out = (float*)d_out;                // (512, 128)     fp32
    cudaFuncSetAttribute(shapelet_mma_kernel,
                         cudaFuncAttributeMaxDynamicSharedMemorySize, SMEM_BYTES);
    shapelet_mma_kernel<<<B_, THREADS, SMEM_BYTES>>>(x, sh, out);
}

// round 10
// speedup vs baseline: 1.1488x; 1.1478x over previous
#include <cuda_runtime.h>
#include <cstdint>

#define S_ 128
#define T_ 2048
#define P_ 1985
#define THREADS 512
#define GRID 296          // 148 SMs x 2 CTAs: one persistent wave
#define NTASKS 1024       // 512 samples x 2 window-halves (1024 windows each)
#define BPSTRIDE 33       // u32 stride for packed shapelet rows

__device__ unsigned g_ctr;   // work-stealing task counter (reset each launch)

static __device__ __forceinline__ uint32_t pack_bf16x2(float lo, float hi) {
    uint32_t r;  // d.hi = cvt(%1), d.lo = cvt(%2)
    asm("cvt.rn.bf16x2.f32 %0, %1, %2;" : "=r"(r) : "f"(hi), "f"(lo));
    return r;
}

// bf16 m16n8k16: D = A*B + {c01,c01,c23,c23}
static __device__ __forceinline__ void mma16_init(float d[4],
        uint32_t a0, uint32_t a1, uint32_t a2, uint32_t a3,
        uint32_t b0, uint32_t b1, float c01, float c23) {
    asm volatile(
        "mma.sync.aligned.m16n8k16.row.col.f32.bf16.bf16.f32 "
        "{%0,%1,%2,%3}, {%4,%5,%6,%7}, {%8,%9}, {%10,%10,%11,%11};"
        : "=f"(d[0]), "=f"(d[1]), "=f"(d[2]), "=f"(d[3])
        : "r"(a0), "r"(a1), "r"(a2), "r"(a3), "r"(b0), "r"(b1),
          "f"(c01), "f"(c23));
}
// bf16 m16n8k16: D = A*B + D
static __device__ __forceinline__ void mma16_acc(float d[4],
        uint32_t a0, uint32_t a1, uint32_t a2, uint32_t a3,
        uint32_t b0, uint32_t b1) {
    asm volatile(
        "mma.sync.aligned.m16n8k16.row.col.f32.bf16.bf16.f32 "
        "{%0,%1,%2,%3}, {%4,%5,%6,%7}, {%8,%9}, {%0,%1,%2,%3};"
        : "+f"(d[0]), "+f"(d[1]), "+f"(d[2]), "+f"(d[3])
        : "r"(a0), "r"(a1), "r"(a2), "r"(a3), "r"(b0), "r"(b1));
}

// init: out = +inf (so atomicMin on bit patterns works), counter = 0
__global__ void init_kernel(unsigned* __restrict__ outb) {
    int i = blockIdx.x * blockDim.x + threadIdx.x;
    if (i < 512 * S_) outb[i] = 0x7F800000u;
    if (i == 0) g_ctr = 0u;
}

// Persistent CTAs steal (sample, half) tasks. Shapelet fragments loaded once
// per CTA. acc = 2*dot - ||p_c||^2 via C-operand init; min d2 = s2 - max(acc).
__global__ void __launch_bounds__(THREADS, 2)
shapelet_mma_kernel(const float* __restrict__ x,
                    const float* __restrict__ sh,
                    float* __restrict__ out) {
    // static smem: 32KB -> 2 CTAs/SM
    __shared__ float    xr[1152];            // raw x segment, zero-padded
    __shared__ uint32_t xp[1152];            // bf16 pairs (x[i], x[i+1])
    __shared__ uint32_t Bp[128 * BPSTRIDE];  // 2*(s-mean) bf16 pairs
    __shared__ float    p2cn[1088];          // NEGATED centered window sq-norm
    __shared__ float    s2[S_];              // RAW shapelet sq-norm
    __shared__ float    wmax[256];
    __shared__ unsigned stsk;

    const int tid = threadIdx.x;
    const int wid = tid >> 5, lane = tid & 31;
    const int gid = lane >> 2, tig = lane & 3;

    // ---- once per CTA: shapelets -> Bp (2*(s-mean) bf16), s2 raw ----
    if (tid < S_) {
        const float* sp = sh + tid * 64;
        float sm = 0.f, q2raw = 0.f;
#pragma unroll
        for (int l = 0; l < 64; ++l) {
            float v = sp[l];
            sm += v;
            q2raw = fmaf(v, v, q2raw);
        }
        float mean = sm * (1.f / 64.f);
#pragma unroll
        for (int l = 0; l < 32; ++l)
            Bp[tid * BPSTRIDE + l] =
                pack_bf16x2(2.f * (sp[2 * l] - mean), 2.f * (sp[2 * l + 1] - mean));
        s2[tid] = q2raw;
    }
    __syncthreads();

    // ---- once per CTA: persistent B fragments ----
    const int h2 = wid >> 3, q = wid & 7;
    uint32_t Bf[2][4][2];
#pragma unroll
    for (int nc = 0; nc < 2; ++nc) {
        int row = q * 16 + nc * 8 + gid;
#pragma unroll
        for (int kc = 0; kc < 4; ++kc) {
            Bf[nc][kc][0] = Bp[row * BPSTRIDE + tig + 8 * kc];
            Bf[nc][kc][1] = Bp[row * BPSTRIDE + tig + 4 + 8 * kc];
        }
    }
    unsigned* outb = reinterpret_cast<unsigned*>(out);

    // ================= task loop =================
    for (;;) {
        if (tid == 0) stsk = atomicAdd(&g_ctr, 1u);
        __syncthreads();
        const unsigned task = stsk;
        if (task >= NTASKS) break;
        const int b = (int)(task >> 1), hh = (int)(task & 1);

        // ---- x segment [hh*1024, hh*1024+1152), zero-padded past T ----
        const float* xg = x + (size_t)b * T_ + hh * 1024;
        const int lim = T_ - hh * 1024;   // 2048 or 1024 valid floats
        for (int i = tid; i < 1152; i += THREADS)
            xr[i] = (i < lim) ? xg[i] : 0.f;
        __syncthreads();

        // pack bf16 pairs
        for (int i = tid; i < 1152; i += THREADS) {
            float hi = (i + 1 < 1152) ? xr[i + 1] : 0.f;
            xp[i] = pack_bf16x2(xr[i], hi);
        }
        // window stats (negated), 2 windows/thread, sliding update
        {
            int p0 = tid * 2;
            float s = 0.f, qq = 0.f;
#pragma unroll
            for (int l = 0; l < 64; ++l) {
                float v = xr[p0 + l];
                s += v;
                qq = fmaf(v, v, qq);
            }
            int pg = hh * 1024 + p0;
            p2cn[p0] = (pg < P_) ? -fmaf(-s, s * (1.f / 64.f), qq) : -3.0e30f;
            float vo = xr[p0], vi = xr[p0 + 64];
            s += vi - vo;
            qq += fmaf(vi, vi, -vo * vo);
            p2cn[p0 + 1] = (pg + 1 < P_) ? -fmaf(-s, s * (1.f / 64.f), qq) : -3.0e30f;
            if (tid < 64) p2cn[1024 + tid] = -3.0e30f;   // prefetch pad
        }
        __syncthreads();

        // ---- main loop: 32 m-groups of 16 windows ----
        float mn[4] = {-3.4e38f, -3.4e38f, -3.4e38f, -3.4e38f};
        const int mstart = h2 * 512;
        for (int mg = 0; mg < 32; ++mg) {
            const int rbase = mstart + mg * 16 + gid;
            uint32_t v[9];
#pragma unroll
            for (int j = 0; j < 9; ++j) v[j] = xp[rbase + 2 * tig + 8 * j];
            const float pc0 = p2cn[rbase], pc1 = p2cn[rbase + 8];

            float A0[4], A1[4];
            mma16_init(A0, v[0], v[1], v[1], v[2], Bf[0][0][0], Bf[0][0][1], pc0, pc1);
            mma16_init(A1, v[0], v[1], v[1], v[2], Bf[1][0][0], Bf[1][0][1], pc0, pc1);
#pragma unroll
            for (int kc = 1; kc < 4; ++kc) {
                mma16_acc(A0, v[2 * kc], v[2 * kc + 1], v[2 * kc + 1], v[2 * kc + 2],
                          Bf[0][kc][0], Bf[0][kc][1]);
                mma16_acc(A1, v[2 * kc], v[2 * kc + 1], v[2 * kc + 1], v[2 * kc + 2],
                          Bf[1][kc][0], Bf[1][kc][1]);
            }
            mn[0] = fmaxf(mn[0], fmaxf(A0[0], A0[2]));
            mn[1] = fmaxf(mn[1], fmaxf(A0[1], A0[3]));
            mn[2] = fmaxf(mn[2], fmaxf(A1[0], A1[2]));
            mn[3] = fmaxf(mn[3], fmaxf(A1[1], A1[3]));
        }

        // ---- reduce (max) over the 8 row-groups ----
#pragma unroll
        for (int i = 0; i < 4; ++i) {
            int nc = i >> 1, e = i & 1;
            float m = mn[i];
            m = fmaxf(m, __shfl_xor_sync(0xffffffffu, m, 4));
            m = fmaxf(m, __shfl_xor_sync(0xffffffffu, m, 8));
            m = fmaxf(m, __shfl_xor_sync(0xffffffffu, m, 16));
            if (lane < 4)
                wmax[h2 * 128 + q * 16 + nc * 8 + lane * 2 + e] = m;
        }
        __syncthreads();

        // ---- dist = sqrt(max(s2 - max(acc), 0)); merge halves via atomicMin ----
        if (tid < S_) {
            float mv = fmaxf(wmax[tid], wmax[128 + tid]);
            float dist = sqrtf(fmaxf(s2[tid] - mv, 0.f));
            atomicMin(&outb[b * S_ + tid], __float_as_uint(dist));
        }
        __syncthreads();   // protect xr/xp/p2cn/wmax before next task
    }
}

extern "C" void kernel_launch(void* const* d_in, const int* in_sizes, int n_in,
                              void* d_out, int out_size) {
    const float* x  = (const float*)d_in[0];   // (512, 1, 2048) fp32
    const float* sh = (const float*)d_in[1];   // (128, 1, 64)   fp32
    float* out = (float*)d_out;                // (512, 128)     fp32
    init_kernel<<<(512 * S_ + 255) / 256, 256>>>((unsigned*)d_out);
    shapelet_mma_kernel<<<GRID, THREADS>>>(x, sh, out);
}

// round 11
// speedup vs baseline: 1.1659x; 1.0148x over previous
#include <cuda_runtime.h>
#include <cstdint>

#define S_ 128
#define T_ 2048
#define P_ 1985
#define THREADS 512
#define GRID 296          // 148 SMs x 2 CTAs: one persistent wave
#define NTASKS 1024       // 512 samples x 2 window-halves (1024 windows each)
#define BPSTRIDE 33       // u32 stride for packed shapelet rows

__device__ unsigned g_ctr;   // work-stealing task counter (reset each launch)

static __device__ __forceinline__ uint32_t pack_bf16x2(float lo, float hi) {
    uint32_t r;  // d.hi = cvt(%1), d.lo = cvt(%2)
    asm("cvt.rn.bf16x2.f32 %0, %1, %2;" : "=r"(r) : "f"(hi), "f"(lo));
    return r;
}

// bf16 m16n8k16: D = A*B + {c01,c01,c23,c23}
static __device__ __forceinline__ void mma16_init(float d[4],
        uint32_t a0, uint32_t a1, uint32_t a2, uint32_t a3,
        uint32_t b0, uint32_t b1, float c01, float c23) {
    asm volatile(
        "mma.sync.aligned.m16n8k16.row.col.f32.bf16.bf16.f32 "
        "{%0,%1,%2,%3}, {%4,%5,%6,%7}, {%8,%9}, {%10,%10,%11,%11};"
        : "=f"(d[0]), "=f"(d[1]), "=f"(d[2]), "=f"(d[3])
        : "r"(a0), "r"(a1), "r"(a2), "r"(a3), "r"(b0), "r"(b1),
          "f"(c01), "f"(c23));
}
// bf16 m16n8k16: D = A*B + D
static __device__ __forceinline__ void mma16_acc(float d[4],
        uint32_t a0, uint32_t a1, uint32_t a2, uint32_t a3,
        uint32_t b0, uint32_t b1) {
    asm volatile(
        "mma.sync.aligned.m16n8k16.row.col.f32.bf16.bf16.f32 "
        "{%0,%1,%2,%3}, {%4,%5,%6,%7}, {%8,%9}, {%0,%1,%2,%3};"
        : "+f"(d[0]), "+f"(d[1]), "+f"(d[2]), "+f"(d[3])
        : "r"(a0), "r"(a1), "r"(a2), "r"(a3), "r"(b0), "r"(b1));
}

// init: out = +inf (so atomicMin on bit patterns works), counter = 0
__global__ void init_kernel(unsigned* __restrict__ outb) {
    int i = blockIdx.x * blockDim.x + threadIdx.x;
    if (i < 512 * S_) outb[i] = 0x7F800000u;
    if (i == 0) g_ctr = 0u;
}

// Persistent CTAs steal (sample, half) tasks. Shapelet fragments loaded once
// per CTA. acc = 2*dot - ||p_c||^2 via C-operand init; min d2 = s2 - max(acc).
__global__ void __launch_bounds__(THREADS, 2)
shapelet_mma_kernel(const float* __restrict__ x,
                    const float* __restrict__ sh,
                    float* __restrict__ out) {
    // static smem: 32KB -> 2 CTAs/SM
    __shared__ float    xr[1152];            // raw x segment, zero-padded
    __shared__ uint32_t xp[1152];            // bf16 pairs (x[i], x[i+1])
    __shared__ uint32_t Bp[128 * BPSTRIDE];  // 2*(s-mean) bf16 pairs
    __shared__ float    p2cn[1088];          // NEGATED centered window sq-norm
    __shared__ float    s2[S_];              // RAW shapelet sq-norm
    __shared__ float    wmax[256];
    __shared__ unsigned stsk;

    const int tid = threadIdx.x;
    const int wid = tid >> 5, lane = tid & 31;
    const int gid = lane >> 2, tig = lane & 3;

    // ---- once per CTA: shapelets -> Bp (2*(s-mean) bf16), s2 raw ----
    if (tid < S_) {
        const float* sp = sh + tid * 64;
        float sm = 0.f, q2raw = 0.f;
#pragma unroll
        for (int l = 0; l < 64; ++l) {
            float v = sp[l];
            sm += v;
            q2raw = fmaf(v, v, q2raw);
        }
        float mean = sm * (1.f / 64.f);
#pragma unroll
        for (int l = 0; l < 32; ++l)
            Bp[tid * BPSTRIDE + l] =
                pack_bf16x2(2.f * (sp[2 * l] - mean), 2.f * (sp[2 * l + 1] - mean));
        s2[tid] = q2raw;
    }
    __syncthreads();

    // ---- once per CTA: persistent B fragments ----
    const int h2 = wid >> 3, q = wid & 7;
    uint32_t Bf[2][4][2];
#pragma unroll
    for (int nc = 0; nc < 2; ++nc) {
        int row = q * 16 + nc * 8 + gid;
#pragma unroll
        for (int kc = 0; kc < 4; ++kc) {
            Bf[nc][kc][0] = Bp[row * BPSTRIDE + tig + 8 * kc];
            Bf[nc][kc][1] = Bp[row * BPSTRIDE + tig + 4 + 8 * kc];
        }
    }
    unsigned* outb = reinterpret_cast<unsigned*>(out);

    // ================= task loop =================
    for (;;) {
        if (tid == 0) stsk = atomicAdd(&g_ctr, 1u);
        __syncthreads();
        const unsigned task = stsk;
        if (task >= NTASKS) break;
        const int b = (int)(task >> 1), hh = (int)(task & 1);

        // ---- x segment [hh*1024, hh*1024+1152), zero-padded past T ----
        const float* xg = x + (size_t)b * T_ + hh * 1024;
        const int lim = T_ - hh * 1024;   // 2048 or 1024 valid floats
        for (int i = tid; i < 1152; i += THREADS)
            xr[i] = (i < lim) ? xg[i] : 0.f;
        __syncthreads();

        // pack bf16 pairs
        for (int i = tid; i < 1152; i += THREADS) {
            float hi = (i + 1 < 1152) ? xr[i + 1] : 0.f;
            xp[i] = pack_bf16x2(xr[i], hi);
        }
        // window stats (negated), 2 windows/thread, sliding update
        {
            int p0 = tid * 2;
            float s = 0.f, qq = 0.f;
#pragma unroll
            for (int l = 0; l < 64; ++l) {
                float v = xr[p0 + l];
                s += v;
                qq = fmaf(v, v, qq);
            }
            int pg = hh * 1024 + p0;
            p2cn[p0] = (pg < P_) ? -fmaf(-s, s * (1.f / 64.f), qq) : -3.0e30f;
            float vo = xr[p0], vi = xr[p0 + 64];
            s += vi - vo;
            qq += fmaf(vi, vi, -vo * vo);
            p2cn[p0 + 1] = (pg + 1 < P_) ? -fmaf(-s, s * (1.f / 64.f), qq) : -3.0e30f;
            if (tid < 64) p2cn[1024 + tid] = -3.0e30f;   // prefetch pad
        }
        __syncthreads();

        // ---- main loop: 32 m-groups of 16 windows ----
        float mn[4] = {-3.4e38f, -3.4e38f, -3.4e38f, -3.4e38f};
        const int mstart = h2 * 512;
        for (int mg = 0; mg < 32; ++mg) {
            const int rbase = mstart + mg * 16 + gid;
            uint32_t v[9];
#pragma unroll
            for (int j = 0; j < 9; ++j) v[j] = xp[rbase + 2 * tig + 8 * j];
            const float pc0 = p2cn[rbase], pc1 = p2cn[rbase + 8];

            float A0[4], A1[4];
            mma16_init(A0, v[0], v[1], v[1], v[2], Bf[0][0][0], Bf[0][0][1], pc0, pc1);
            mma16_init(A1, v[0], v[1], v[1], v[2], Bf[1][0][0], Bf[1][0][1], pc0, pc1);
#pragma unroll
            for (int kc = 1; kc < 4; ++kc) {
                mma16_acc(A0, v[2 * kc], v[2 * kc + 1], v[2 * kc + 1], v[2 * kc + 2],
                          Bf[0][kc][0], Bf[0][kc][1]);
                mma16_acc(A1, v[2 * kc], v[2 * kc + 1], v[2 * kc + 1], v[2 * kc + 2],
                          Bf[1][kc][0], Bf[1][kc][1]);
            }
            mn[0] = fmaxf(mn[0], fmaxf(A0[0], A0[2]));
            mn[1] = fmaxf(mn[1], fmaxf(A0[1], A0[3]));
            mn[2] = fmaxf(mn[2], fmaxf(A1[0], A1[2]));
            mn[3] = fmaxf(mn[3], fmaxf(A1[1], A1[3]));
        }

        // ---- reduce (max) over the 8 row-groups ----
#pragma unroll
        for (int i = 0; i < 4; ++i) {
            int nc = i >> 1, e = i & 1;
            float m = mn[i];
            m = fmaxf(m, __shfl_xor_sync(0xffffffffu, m, 4));
            m = fmaxf(m, __shfl_xor_sync(0xffffffffu, m, 8));
            m = fmaxf(m, __shfl_xor_sync(0xffffffffu, m, 16));
            if (lane < 4)
                wmax[h2 * 128 + q * 16 + nc * 8 + lane * 2 + e] = m;
        }
        __syncthreads();

        // ---- dist = sqrt(max(s2 - max(acc), 0)); merge halves via atomicMin ----
        if (tid < S_) {
            float mv = fmaxf(wmax[tid], wmax[128 + tid]);
            float dist = sqrtf(fmaxf(s2[tid] - mv, 0.f));
            atomicMin(&outb[b * S_ + tid], __float_as_uint(dist));
        }
        __syncthreads();   // protect xr/xp/p2cn/wmax before next task
    }
}

extern "C" void kernel_launch(void* const* d_in, const int* in_sizes, int n_in,
                              void* d_out, int out_size) {
    const float* x  = (const float*)d_in[0];   // (512, 1, 2048) fp32
    const float* sh = (const float*)d_in[1];   // (128, 1, 64)   fp32
    float* out = (float*)d_out;                // (512, 128)     fp32
    init_kernel<<<(512 * S_ + 255) / 256, 256>>>((unsigned*)d_out);
    shapelet_mma_kernel<<<GRID, THREADS>>>(x, sh, out);
}